// round 9
// baseline (speedup 1.0000x reference)
#include <cuda_runtime.h>

#define NFFT 16000
#define NH   8000
#define BT   800
// 16000-domain padding (forward stages)
#define PHI(i)  ((i) + 6 * ((i) / 100))
#define SMPAD   (NFFT + 6 * (NFFT / 100))        // 16960 float2
// 8000-domain padding (inverse stages), separate region
#define PHI8(i) ((i) + 3 * ((i) / 50))
#define SMPAD8  (NH + 3 * (NH / 50))             // 8480 float2
#define SMTOTAL ((SMPAD + SMPAD8) * sizeof(float2))  // 203,520 B

// Forward plan (DIF) on 16000: 16,10,10,10 -> strides 1000,100,10,1
// Inverse plan (DIT) on 8000:  [16,10,10,5]; see earlier rounds for the digit maps.

typedef unsigned long long u64;

__device__ __align__(16) float2 g_tw[NFFT];      // e^{-2*pi*i*t/16000}
__device__ __align__(16) float2 g_twf1000[100];  // g_tw[16*n2]
__device__ __align__(16) float2 g_twf100[16];    // g_tw[160*n2]
__device__ __align__(16) float2 g_twi50[8];      // conj g_tw[320*n2]
__device__ __align__(16) float2 g_twi500[56];    // conj g_tw[32*n2]
__device__ __align__(16) float2 g_twi8000[500];  // conj g_tw[2*n2]

__global__ void init_tables_kernel() {
    int p = blockIdx.x * blockDim.x + threadIdx.x;
    if (p < NFFT) {
        double ang = -2.0 * 3.14159265358979323846 * (double)p / (double)NFFT;
        g_tw[p] = make_float2((float)cos(ang), (float)sin(ang));
    }
    if (p < 100) {
        double a = -2.0 * 3.14159265358979323846 * (double)(16 * p) / (double)NFFT;
        g_twf1000[p] = make_float2((float)cos(a), (float)sin(a));
    }
    if (p < 10) {
        double a = -2.0 * 3.14159265358979323846 * (double)(160 * p) / (double)NFFT;
        g_twf100[p] = make_float2((float)cos(a), (float)sin(a));
    }
    if (p < 5) {
        double a = 2.0 * 3.14159265358979323846 * (double)(320 * p) / (double)NFFT;
        g_twi50[p] = make_float2((float)cos(a), (float)sin(a));
    }
    if (p < 50) {
        double a = 2.0 * 3.14159265358979323846 * (double)(32 * p) / (double)NFFT;
        g_twi500[p] = make_float2((float)cos(a), (float)sin(a));
    }
    if (p < 500) {
        double a = 2.0 * 3.14159265358979323846 * (double)(2 * p) / (double)NFFT;
        g_twi8000[p] = make_float2((float)cos(a), (float)sin(a));
    }
}

__device__ __forceinline__ int block_of(int f0) {
    return 100 * (f0 & 15) + 10 * ((f0 >> 4) % 10) + (f0 / 160);
}

// ---- packed complex type: one 64-bit register pair holding (re, im) ----
struct cx { u64 v; };

__device__ __forceinline__ cx mkcx2(float x, float y) {
    cx r; asm("mov.b64 %0, {%1, %2};" : "=l"(r.v) : "f"(x), "f"(y)); return r;
}
__device__ __forceinline__ void cxup(cx a, float& x, float& y) {
    asm("mov.b64 {%0, %1}, %2;" : "=f"(x), "=f"(y) : "l"(a.v));
}
__device__ __forceinline__ u64 dup2(float c) {
    u64 r; asm("mov.b64 %0, {%1, %1};" : "=l"(r) : "f"(c)); return r;
}
__device__ __forceinline__ cx cadd(cx a, cx b) {
    cx r; asm("add.rn.f32x2 %0, %1, %2;" : "=l"(r.v) : "l"(a.v), "l"(b.v)); return r;
}
__device__ __forceinline__ cx csub(cx a, cx b) {   // a - b = fma(b, {-1,-1}, a), exact
    const u64 NEG1 = 0xBF800000BF800000ULL;
    cx r; asm("fma.rn.f32x2 %0, %1, %2, %3;" : "=l"(r.v) : "l"(b.v), "l"(NEG1), "l"(a.v)); return r;
}
__device__ __forceinline__ cx cfmaK(u64 cc, cx t, cx acc) {  // {c,c}*t + acc
    cx r; asm("fma.rn.f32x2 %0, %1, %2, %3;" : "=l"(r.v) : "l"(t.v), "l"(cc), "l"(acc.v)); return r;
}
__device__ __forceinline__ cx cmulK(u64 cc, cx t) {          // {c,c}*t
    cx r; asm("mul.rn.f32x2 %0, %1, %2;" : "=l"(r.v) : "l"(t.v), "l"(cc)); return r;
}
// cross-lane ops stay scalar
__device__ __forceinline__ cx cmul(cx a, cx b) {
    float ax, ay, bx, by; cxup(a, ax, ay); cxup(b, bx, by);
    return mkcx2(fmaf(ax, bx, -ay * by), fmaf(ax, by, ay * bx));
}
__device__ __forceinline__ cx cmulc(cx a, float cr, float ci) {
    float x, y; cxup(a, x, y);
    return mkcx2(fmaf(x, cr, -y * ci), fmaf(x, ci, y * cr));
}
template <int DIR>
__device__ __forceinline__ cx cmuli(cx a) {   // * (DIR*i)
    float x, y; cxup(a, x, y);
    return (DIR > 0) ? mkcx2(-y, x) : mkcx2(y, -x);
}
__device__ __forceinline__ cx conj64(cx a) { cx r; r.v = a.v ^ 0x8000000000000000ULL; return r; }

template <int DIR>
__device__ __forceinline__ void dft4(cx* x) {
    cx t0 = cadd(x[0], x[2]);
    cx t1 = csub(x[0], x[2]);
    cx t2 = cadd(x[1], x[3]);
    cx u  = csub(x[1], x[3]);
    x[0] = cadd(t0, t2);
    x[2] = csub(t0, t2);
    float t1x, t1y, ux, uy; cxup(t1, t1x, t1y); cxup(u, ux, uy);
    const float D = (float)DIR;   // i*D*u = (-D*uy, D*ux)
    x[1] = mkcx2(t1x - D * uy, t1y + D * ux);
    x[3] = mkcx2(t1x + D * uy, t1y - D * ux);
}

template <int DIR>
__device__ __forceinline__ void dft5(cx* x) {
    const u64 Kc1 = dup2(0.30901699437494742f);
    const u64 Kc2 = dup2(-0.80901699437494745f);
    const u64 Ks1 = dup2(0.95105651629515357f);
    const u64 Ks2 = dup2(0.58778525229247313f);
    const u64 Kms1 = dup2(-0.95105651629515357f);
    cx t1 = cadd(x[1], x[4]);
    cx t2 = cadd(x[2], x[3]);
    cx t3 = csub(x[1], x[4]);
    cx t4 = csub(x[2], x[3]);
    cx x0 = x[0];
    cx a1 = cfmaK(Kc1, t1, cfmaK(Kc2, t2, x0));
    cx a2 = cfmaK(Kc2, t1, cfmaK(Kc1, t2, x0));
    cx b1 = cfmaK(Ks1, t3, cmulK(Ks2, t4));
    cx b2 = cfmaK(Ks2, t3, cmulK(Kms1, t4));
    x[0] = cadd(x0, cadd(t1, t2));
    float a1x, a1y, a2x, a2y, b1x, b1y, b2x, b2y;
    cxup(a1, a1x, a1y); cxup(b1, b1x, b1y);
    cxup(a2, a2x, a2y); cxup(b2, b2x, b2y);
    const float D = (float)DIR;   // ib = (-D*by, D*bx); x=a+ib / a-ib
    x[1] = mkcx2(a1x - D * b1y, a1y + D * b1x);
    x[4] = mkcx2(a1x + D * b1y, a1y - D * b1x);
    x[2] = mkcx2(a2x - D * b2y, a2y + D * b2x);
    x[3] = mkcx2(a2x + D * b2y, a2y - D * b2x);
}

// 10-point DFT = 2x5 CT, stride-S register access.
template <int DIR, int S>
__device__ __forceinline__ void dft10s(cx* x) {
    const float C36 = 0.80901699437494742f;
    const float S36 = 0.58778525229247313f;
    const float C72 = 0.30901699437494742f;
    const float S72 = 0.95105651629515357f;
    const float D = (float)DIR;
    cx a[5], c[5];
#pragma unroll
    for (int k = 0; k < 5; k++) {
        a[k] = cadd(x[k * S], x[(k + 5) * S]);
        c[k] = csub(x[k * S], x[(k + 5) * S]);
    }
    c[1] = cmulc(c[1], C36, D * S36);
    c[2] = cmulc(c[2], C72, D * S72);
    c[3] = cmulc(c[3], -C72, D * S72);
    c[4] = cmulc(c[4], -C36, D * S36);
    dft5<DIR>(a);
    dft5<DIR>(c);
    x[0 * S] = a[0]; x[2 * S] = a[1]; x[4 * S] = a[2]; x[6 * S] = a[3]; x[8 * S] = a[4];
    x[1 * S] = c[0]; x[3 * S] = c[1]; x[5 * S] = c[2]; x[7 * S] = c[3]; x[9 * S] = c[4];
}

// 16-point DFT = 4x4 CT, stride-S register access.
template <int DIR, int S>
__device__ __forceinline__ void dft16s(cx* x) {
    const float C1 = 0.92387953251128674f;
    const float S1 = 0.38268343236508978f;
    const float C2 = 0.70710678118654752f;
    const float D = (float)DIR;
    cx y[16];
#pragma unroll
    for (int n2 = 0; n2 < 4; n2++) {
        cx t[4] = {x[n2 * S], x[(n2 + 4) * S], x[(n2 + 8) * S], x[(n2 + 12) * S]};
        dft4<DIR>(t);
        if (n2 == 1) {
            t[1] = cmulc(t[1], C1, D * S1);
            t[2] = cmulc(t[2], C2, D * C2);
            t[3] = cmulc(t[3], S1, D * C1);
        } else if (n2 == 2) {
            t[1] = cmulc(t[1], C2, D * C2);
            t[2] = cmuli<DIR>(t[2]);
            t[3] = cmulc(t[3], -C2, D * C2);
        } else if (n2 == 3) {
            t[1] = cmulc(t[1], S1, D * C1);
            t[2] = cmulc(t[2], -C2, D * C2);
            t[3] = cmulc(t[3], -C1, -D * S1);
        }
        y[0 + n2] = t[0]; y[4 + n2] = t[1]; y[8 + n2] = t[2]; y[12 + n2] = t[3];
    }
#pragma unroll
    for (int k1 = 0; k1 < 4; k1++) {
        cx t[4] = {y[k1 * 4 + 0], y[k1 * 4 + 1], y[k1 * 4 + 2], y[k1 * 4 + 3]};
        dft4<DIR>(t);
        x[(k1 + 0) * S] = t[0]; x[(k1 + 4) * S] = t[1];
        x[(k1 + 8) * S] = t[2]; x[(k1 + 12) * S] = t[3];
    }
}

// Twiddle chains: odd/even accumulators stepping by w^2 (no extra loads).
template <int S>
__device__ __forceinline__ void apply_tw10_chain(cx* x, cx w1) {
    cx w2 = cmul(w1, w1);
    cx wo = w1, we = w2;
    x[1 * S] = cmul(x[1 * S], wo);
    x[2 * S] = cmul(x[2 * S], we);
#pragma unroll
    for (int j = 3; j < 10; j += 2) {
        wo = cmul(wo, w2); x[j * S] = cmul(x[j * S], wo);
        if (j + 1 < 10) { we = cmul(we, w2); x[(j + 1) * S] = cmul(x[(j + 1) * S], we); }
    }
}

template <int S>
__device__ __forceinline__ void apply_tw16_chain(cx* x, cx w1) {
    cx w2 = cmul(w1, w1);
    cx wo = w1, we = w2;
    x[1 * S] = cmul(x[1 * S], wo);
    x[2 * S] = cmul(x[2 * S], we);
#pragma unroll
    for (int j = 3; j < 16; j += 2) {
        wo = cmul(wo, w2); x[j * S] = cmul(x[j * S], wo);
        if (j + 1 < 16) { we = cmul(we, w2); x[(j + 1) * S] = cmul(x[(j + 1) * S], we); }
    }
}

// Forward radix-16 stage (NS=16000, m=1000), DIF, paired via 16B vectors.
__device__ __forceinline__ void stage16_fwd(float2* sm, int tid) {
    if (tid >= 500) return;
    int n2 = 2 * tid;
    cx X[32];
#pragma unroll
    for (int j = 0; j < 16; j++) {
        ulonglong2 t = *(const ulonglong2*)&sm[PHI(n2 + j * 1000)];
        X[2 * j].v = t.x;
        X[2 * j + 1].v = t.y;
    }
    dft16s<-1, 2>(X);
    dft16s<-1, 2>(X + 1);
    ulonglong2 wv = *(const ulonglong2*)&g_tw[n2];
    cx wa; wa.v = wv.x;
    cx wb; wb.v = wv.y;
    apply_tw16_chain<2>(X, wa);
    apply_tw16_chain<2>(X + 1, wb);
#pragma unroll
    for (int j = 0; j < 16; j++) {
        *(ulonglong2*)&sm[PHI(n2 + j * 1000)] = make_ulonglong2(X[2 * j].v, X[2 * j + 1].v);
    }
}

// Forward radix-10 stage, two adjacent butterflies per thread; 800 tasks = BT.
template <int NS>
__device__ __forceinline__ void stage10_paired(float2* sm, int tid, const float2* __restrict__ tab) {
    constexpr int m = NS / 10;
    constexpr int halfm = m / 2;
    int blk = tid / halfm;
    int h = tid - blk * halfm;
    int n2 = 2 * h;
    int base = blk * NS + n2;
    cx X[20];
#pragma unroll
    for (int j = 0; j < 10; j++) {
        ulonglong2 t = *(const ulonglong2*)&sm[PHI(base + j * m)];
        X[2 * j].v = t.x;
        X[2 * j + 1].v = t.y;
    }
    ulonglong2 wv = *(const ulonglong2*)&tab[n2];
    cx wa; wa.v = wv.x;
    cx wb; wb.v = wv.y;
    dft10s<-1, 2>(X);
    apply_tw10_chain<2>(X, wa);
    dft10s<-1, 2>(X + 1);
    apply_tw10_chain<2>(X + 1, wb);
#pragma unroll
    for (int j = 0; j < 10; j++) {
        *(ulonglong2*)&sm[PHI(base + j * m)] = make_ulonglong2(X[2 * j].v, X[2 * j + 1].v);
    }
}

// Inverse (DIT) stage on the 8000-point array; w1 from pre-conjugated coalesced table.
template <int R, int NS, bool TO_GMEM>
__device__ __forceinline__ void stage8_inv(float2* s8, int tid, float2* __restrict__ gout2,
                                           const float2* __restrict__ tab) {
    constexpr int m = NS / R;
    constexpr int nb = NH / R;
    for (int u = tid; u < nb; u += BT) {
        int blk = u / m;
        int n2 = u - blk * m;
        int base = blk * NS + n2;
        cx x[R];
#pragma unroll
        for (int j = 0; j < R; j++) x[j].v = *(const u64*)&s8[PHI8(base + j * m)];
        cx w1; w1.v = *(const u64*)&tab[n2];
        if constexpr (R == 16) {
            apply_tw16_chain<1>(x, w1);
            dft16s<1, 1>(x);
        } else {
            apply_tw10_chain<1>(x, w1);
            dft10s<1, 1>(x);
        }
#pragma unroll
        for (int j = 0; j < R; j++) {
            if constexpr (TO_GMEM) *(u64*)&gout2[base + j * m] = x[j].v;
            else *(u64*)&s8[PHI8(base + j * m)] = x[j].v;
        }
    }
}

__device__ __forceinline__ void pw(cx& A, cx& C, float scale) {
    float ax, ay, ccx, ccy;
    cxup(A, ax, ay); cxup(C, ccx, ccy);
    float Fix = ax + ccx, Fiy = ay - ccy;
    float Fsx = ay + ccy, Fsy = -(ax - ccx);
    float Zx = fmaf(Fix, Fsx, -Fiy * Fsy) * scale;
    float Zy = fmaf(Fix, Fsy, Fiy * Fsx) * scale;
    A = mkcx2(Zx, Zy);
    C = mkcx2(Zx, -Zy);
}

// Pack 10 Z-values (f = f0+1600t) into 5 C-values of the 8000-domain,
// then inverse radix-5 (m=1); store at s8[PHI8(5b)+j].
__device__ __forceinline__ void pack_inv5_store(const cx* x, cx w0, float2* s8, int b) {
    const float RC[5] = {1.f, 0.80901699437494742f, 0.30901699437494742f,
                         -0.30901699437494742f, -0.80901699437494742f};
    const float RS[5] = {0.f, 0.58778525229247313f, 0.95105651629515357f,
                         0.95105651629515357f, 0.58778525229247313f};
    cx C[5];
#pragma unroll
    for (int t = 0; t < 5; t++) {
        cx S = cadd(x[t], x[t + 5]);
        cx Dd = csub(x[t], x[t + 5]);
        cx wt = (t == 0) ? w0 : cmul(w0, mkcx2(RC[t], RS[t]));
        cx m = cmul(wt, Dd);
        float Sx, Sy, mx, my; cxup(S, Sx, Sy); cxup(m, mx, my);
        C[t] = mkcx2(Sx - my, Sy + mx);   // S + i*m
    }
    dft5<1>(C);
    int base = PHI8(5 * b);
#pragma unroll
    for (int j = 0; j < 5; j++) *(u64*)&s8[base + j] = C[j].v;
}

// Fused middle: forward radix-10 (m=1) + Hermitian pointwise + pack + inverse radix-5.
__device__ __forceinline__ void fused_mid(float2* sm, float2* s8, int tid) {
    const float scale = 0.25f / (float)NFFT;
    int fa, fb;
    if (tid < 799) { fa = tid + 1; fb = 1600 - fa; }
    else           { fa = 0;       fb = 800; }
    int b  = block_of(fa);
    int b2 = block_of(fb);
    int pa = PHI(10 * b);
    int pb = PHI(10 * b2);
    cx xa[10], xb[10];
#pragma unroll
    for (int k = 0; k < 5; k++) {
        ulonglong2 t = *(const ulonglong2*)&sm[pa + 2 * k];
        xa[2 * k].v = t.x; xa[2 * k + 1].v = t.y;
        ulonglong2 s = *(const ulonglong2*)&sm[pb + 2 * k];
        xb[2 * k].v = s.x; xb[2 * k + 1].v = s.y;
    }
    dft10s<-1, 1>(xa);
    dft10s<-1, 1>(xb);
    if (tid < 799) {
#pragma unroll
        for (int t = 0; t < 10; t++) pw(xa[t], xb[9 - t], scale);
    } else {
        pw(xa[0], xa[0], scale);
        pw(xa[5], xa[5], scale);
        pw(xa[1], xa[9], scale);
        pw(xa[2], xa[8], scale);
        pw(xa[3], xa[7], scale);
        pw(xa[4], xa[6], scale);
        pw(xb[0], xb[9], scale);
        pw(xb[1], xb[8], scale);
        pw(xb[2], xb[7], scale);
        pw(xb[3], xb[6], scale);
        pw(xb[4], xb[5], scale);
    }
    cx ta; ta.v = *(const u64*)&g_tw[fa];
    cx tb; tb.v = *(const u64*)&g_tw[fb];
    ta = conj64(ta);   // e^{+2pi i fa/16000}
    tb = conj64(tb);
    pack_inv5_store(xa, ta, s8, b);
    pack_inv5_store(xb, tb, s8, b2);
}

__global__ void __launch_bounds__(BT) mcb_main_kernel(
    const float* __restrict__ img, const float* __restrict__ seq,
    const int* __restrict__ hv, const float* __restrict__ sv,
    float* __restrict__ out, int d) {
    extern __shared__ float2 sm[];
    float2* s8 = sm + SMPAD;
    const int b = blockIdx.x;
    const int tid = threadIdx.x;

    float4* sm4 = (float4*)sm;
    for (int i = tid; i < SMPAD / 2; i += BT) sm4[i] = make_float4(0.f, 0.f, 0.f, 0.f);
    __syncthreads();

    const float* irow = img + (size_t)b * d;
    const float* qrow = seq + (size_t)b * d;
    for (int i = tid; i < d; i += BT) {
        int h = PHI(hv[i]);
        float s = sv[i];
        atomicAdd(&sm[h].x, irow[i] * s);
        atomicAdd(&sm[h].y, qrow[i] * s);
    }
    __syncthreads();

    float2* orow2 = (float2*)(out + (size_t)b * NFFT);

    // forward 16000: 16 (paired), 10, 10 | fused(10 + pointwise + pack + inv5)
    stage16_fwd(sm, tid);                       __syncthreads();
    stage10_paired<1000>(sm, tid, g_twf1000);   __syncthreads();
    stage10_paired<100>(sm, tid, g_twf100);     __syncthreads();
    fused_mid(sm, s8, tid);                     __syncthreads();
    // inverse 8000: 10 (m=5), 10 (m=50), 16 (m=500) -> gmem float2
    stage8_inv<10, 50, false>(s8, tid, orow2, g_twi50);     __syncthreads();
    stage8_inv<10, 500, false>(s8, tid, orow2, g_twi500);   __syncthreads();
    stage8_inv<16, 8000, true>(s8, tid, orow2, g_twi8000);
}

extern "C" void kernel_launch(void* const* d_in, const int* in_sizes, int n_in,
                              void* d_out, int out_size) {
    const float* img = (const float*)d_in[0];
    const float* seq = (const float*)d_in[1];
    const int* hv = (const int*)d_in[2];
    const float* sv = (const float*)d_in[3];
    float* out = (float*)d_out;

    int d = in_sizes[2];
    int B = in_sizes[0] / d;

    static_assert(NFFT == 16000 && NH == 8000, "plan assumes N=16000");

    cudaFuncSetAttribute(mcb_main_kernel, cudaFuncAttributeMaxDynamicSharedMemorySize,
                         SMTOTAL);

    init_tables_kernel<<<(NFFT + 255) / 256, 256>>>();
    mcb_main_kernel<<<B, BT, SMTOTAL>>>(img, seq, hv, sv, out, d);
}